// round 1
// baseline (speedup 1.0000x reference)
#include <cuda_runtime.h>
#include <cstdint>

// Problem constants
#define B_  4
#define LQ  512
#define LK  512
#define DQ  256
#define DC  256
#define H_  128

// Scratch (allocation-free rule: __device__ globals)
__device__ float g_qp  [B_ * LQ * H_];      // [row=b*LQ+q][h] : query proj + bq
__device__ float g_c2T [B_ * H_ * LK];      // [b][h][k]       : 2*(context proj + bc)
__device__ float g_attn[B_ * LQ * LK];      // [row][k]        : softmax weights

typedef unsigned long long ull;

// ---------- f32x2 helpers (Blackwell packed fp32) ----------
__device__ __forceinline__ ull pk(float a, float b) {
    ull r; asm("mov.b64 %0, {%1, %2};" : "=l"(r) : "f"(a), "f"(b)); return r;
}
__device__ __forceinline__ void upk(ull v, float& a, float& b) {
    asm("mov.b64 {%0, %1}, %2;" : "=f"(a), "=f"(b) : "l"(v));
}
__device__ __forceinline__ ull add2(ull a, ull b) {
    ull r; asm("add.rn.f32x2 %0, %1, %2;" : "=l"(r) : "l"(a), "l"(b)); return r;
}
__device__ __forceinline__ ull fma2(ull a, ull b, ull c) {
    ull r; asm("fma.rn.f32x2 %0, %1, %2, %3;" : "=l"(r) : "l"(a), "l"(b), "l"(c)); return r;
}
__device__ __forceinline__ float tf(float x) {
    float y; asm("tanh.approx.f32 %0, %1;" : "=f"(y) : "f"(x)); return y;
}

// ---------------------------------------------------------------------------
// Kernel 1: projections.
//   grid.y==0: g_qp[row][h]      = query[row]·Wq[h] + bq[h]
//   grid.y==1: g_c2T[b][h][k]    = 2*(context[row]·Wc[h] + bc[h]),  row=b*LK+k
// 16 rows per CTA, 256 threads (h = t&127, row-group = t>>7).
// ---------------------------------------------------------------------------
__global__ __launch_bounds__(256) void proj_kernel(
    const float* __restrict__ query, const float* __restrict__ context,
    const float* __restrict__ Wq, const float* __restrict__ bq,
    const float* __restrict__ Wc, const float* __restrict__ bc)
{
    __shared__ float insh[16][256];                 // 16 KB input tile

    const bool isC = (blockIdx.y == 1);
    const float* in   = isC ? context : query;
    const float* W    = isC ? Wc : Wq;
    const float* bias = isC ? bc : bq;

    const int t  = threadIdx.x;
    const int r0 = blockIdx.x * 16;

    // cooperative coalesced load of 16x256 input rows
    {
        const float4* src = (const float4*)(in + (size_t)r0 * 256);
        float4* dst = (float4*)insh;
        #pragma unroll
        for (int i = t; i < 16 * 64; i += 256) dst[i] = src[i];
    }
    __syncthreads();

    const int h  = t & 127;
    const int rg = t >> 7;          // 0..1, rows rg*8 .. rg*8+7
    float acc[8];
    const float bb = bias[h];
    #pragma unroll
    for (int j = 0; j < 8; j++) acc[j] = bb;

    const float4* wrow = (const float4*)(W + (size_t)h * 256);
    #pragma unroll 4
    for (int d4 = 0; d4 < 64; d4++) {
        const float4 w4 = wrow[d4];
        #pragma unroll
        for (int j = 0; j < 8; j++) {
            const float4 q4 = *(const float4*)&insh[rg * 8 + j][d4 * 4];  // broadcast LDS
            acc[j] = fmaf(w4.x, q4.x, acc[j]);
            acc[j] = fmaf(w4.y, q4.y, acc[j]);
            acc[j] = fmaf(w4.z, q4.z, acc[j]);
            acc[j] = fmaf(w4.w, q4.w, acc[j]);
        }
    }

    if (!isC) {
        #pragma unroll
        for (int j = 0; j < 8; j++) {
            const int row = r0 + rg * 8 + j;
            g_qp[(size_t)row * H_ + h] = acc[j];      // coalesced over h
        }
    } else {
        #pragma unroll
        for (int j = 0; j < 8; j++) {
            const int row = r0 + rg * 8 + j;
            const int b = row >> 9, k = row & 511;
            g_c2T[((size_t)b * H_ + h) * LK + k] = 2.0f * acc[j];
        }
    }
}

// ---------------------------------------------------------------------------
// Kernel 2: scores + softmax (the MUFU-bound core).
// One CTA per (b, q-pair): 1024 CTAs, 256 threads.
// Thread t handles k = t and k = t+256 for BOTH q's of the pair (f32x2 lanes).
//   score[q][k] = sum_h Wv[h] * tanh(qp[q][h] + c2T[b][h][k])        (bv dropped:
//   constant shift is softmax-invariant)
// Then fused per-q softmax (warp 0 -> q0, warp 1 -> q1), attn -> gmem.
// ---------------------------------------------------------------------------
__global__ __launch_bounds__(256) void scores_kernel(const float* __restrict__ Wv)
{
    __shared__ ull qsh2[H_];        // (qp[q0][h], qp[q1][h]) packed
    __shared__ ull wv2 [H_];        // (Wv[h], Wv[h]) packed
    __shared__ float sc[2][LK];     // scores per q

    const int tile = blockIdx.x;          // 0..1023
    const int b  = tile >> 8;             // 256 tiles per batch
    const int q0 = (tile & 255) * 2;
    const int t  = threadIdx.x;

    if (t < H_) {
        const size_t base = ((size_t)b * LQ + q0) * H_;
        qsh2[t] = pk(g_qp[base + t], g_qp[base + H_ + t]);
        const float w = Wv[t];
        wv2[t] = pk(w, w);
    }
    __syncthreads();

    const float* p0 = g_c2T + (size_t)b * H_ * LK + t;   // k0 = t, k1 = t+256

    ull acc0 = 0ULL, acc1 = 0ULL;
    #pragma unroll 4
    for (int h = 0; h < H_; h++) {
        const float c0 = p0[h * LK];          // coalesced over k
        const float c1 = p0[h * LK + 256];
        const ull q  = qsh2[h];               // broadcast
        const ull wv = wv2[h];                // broadcast
        ull a0 = add2(q, pk(c0, c0));
        ull a1 = add2(q, pk(c1, c1));
        float x0, y0, x1, y1;
        upk(a0, x0, y0); upk(a1, x1, y1);
        x0 = tf(x0); y0 = tf(y0); x1 = tf(x1); y1 = tf(y1);
        acc0 = fma2(pk(x0, y0), wv, acc0);
        acc1 = fma2(pk(x1, y1), wv, acc1);
    }

    float s00, s01, s10, s11;
    upk(acc0, s00, s01);      // (q0,k=t), (q1,k=t)
    upk(acc1, s10, s11);      // (q0,k=t+256), (q1,k=t+256)
    sc[0][t]       = s00;
    sc[1][t]       = s01;
    sc[0][t + 256] = s10;
    sc[1][t + 256] = s11;
    __syncthreads();

    // fused softmax: warp w handles q = q0 + w  (w in {0,1})
    const int w = t >> 5, lane = t & 31;
    if (w < 2) {
        float e[16];
        float m = -1e30f;
        #pragma unroll
        for (int j = 0; j < 16; j++) {
            e[j] = sc[w][lane + j * 32];
            m = fmaxf(m, e[j]);
        }
        #pragma unroll
        for (int off = 16; off > 0; off >>= 1)
            m = fmaxf(m, __shfl_xor_sync(0xffffffffu, m, off));
        float s = 0.0f;
        #pragma unroll
        for (int j = 0; j < 16; j++) { e[j] = __expf(e[j] - m); s += e[j]; }
        #pragma unroll
        for (int off = 16; off > 0; off >>= 1)
            s += __shfl_xor_sync(0xffffffffu, s, off);
        const float inv = 1.0f / s;
        float* dst = g_attn + ((size_t)b * LQ + q0 + w) * LK;
        #pragma unroll
        for (int j = 0; j < 16; j++) dst[lane + j * 32] = e[j] * inv;  // coalesced
    }
}

// ---------------------------------------------------------------------------
// Kernel 3: out[b,q,:] = attn[b,q,:] @ context[b]     (FMA2, L1-friendly)
// Grid 128 CTAs: (b, 16-q tile). Threads: d4 = t&63 (float4 over Dc), qg = t>>6
// (4 q's each). ctx float4 coalesced; attn broadcast from shared.
// ---------------------------------------------------------------------------
__global__ __launch_bounds__(256) void out_kernel(
    const float* __restrict__ context, float* __restrict__ out)
{
    __shared__ float attn_sh[16][LK];     // 32 KB

    const int bx = blockIdx.x;
    const int b  = bx >> 5;               // 32 tiles per batch
    const int q0 = (bx & 31) * 16;
    const int t  = threadIdx.x;

    {
        const float4* src = (const float4*)(g_attn + ((size_t)b * LQ + q0) * LK);
        float4* dst = (float4*)attn_sh;
        #pragma unroll
        for (int i = t; i < 16 * 128; i += 256) dst[i] = src[i];
    }
    __syncthreads();

    const int d4 = t & 63;                // d = d4*4
    const int qg = t >> 6;                // q's qg*4 .. qg*4+3
    const float4* ctx4 = (const float4*)(context + (size_t)b * LK * DC);

    ull acc[4][2];
    #pragma unroll
    for (int qi = 0; qi < 4; qi++) { acc[qi][0] = 0ULL; acc[qi][1] = 0ULL; }

    #pragma unroll 2
    for (int k = 0; k < LK; k++) {
        const float4 c4 = ctx4[k * 64 + d4];          // coalesced 512B/warp
        const ull cxy = pk(c4.x, c4.y);
        const ull czw = pk(c4.z, c4.w);
        #pragma unroll
        for (int qi = 0; qi < 4; qi++) {
            const float a = attn_sh[qg * 4 + qi][k];  // broadcast LDS
            const ull aa = pk(a, a);
            acc[qi][0] = fma2(aa, cxy, acc[qi][0]);
            acc[qi][1] = fma2(aa, czw, acc[qi][1]);
        }
    }

    #pragma unroll
    for (int qi = 0; qi < 4; qi++) {
        float x0, x1, x2, x3;
        upk(acc[qi][0], x0, x1);
        upk(acc[qi][1], x2, x3);
        float4* o = (float4*)(out + ((size_t)b * LQ + q0 + qg * 4 + qi) * DC + d4 * 4);
        *o = make_float4(x0, x1, x2, x3);
    }
}

// ---------------------------------------------------------------------------
extern "C" void kernel_launch(void* const* d_in, const int* in_sizes, int n_in,
                              void* d_out, int out_size)
{
    const float* query   = (const float*)d_in[0];
    const float* context = (const float*)d_in[1];
    const float* Wq      = (const float*)d_in[2];
    const float* bq      = (const float*)d_in[3];
    const float* Wc      = (const float*)d_in[4];
    const float* bc      = (const float*)d_in[5];
    const float* Wv      = (const float*)d_in[6];
    // d_in[7] = bv : constant shift before softmax, mathematically a no-op.

    proj_kernel  <<<dim3(128, 2), 256>>>(query, context, Wq, bq, Wc, bc);
    scores_kernel<<<1024, 256>>>(Wv);
    out_kernel   <<<128, 256>>>(context, (float*)d_out);
}